// round 9
// baseline (speedup 1.0000x reference)
#include <cuda_runtime.h>
#include <math.h>

#define NMODES 64
#define LSEQ   262144
#define SEG    32
#define NSEGS  (LSEQ/SEG)        /* 8192 */
#define GRID   592               /* 148 SMs x 4 blocks: guaranteed co-resident */
#define THR    128
#define CPT    64                /* segs composed per scan thread (128 thr) */
#define LEVELS 7

// ---------------- scratch (static device globals; no allocation) ----------------
__device__ float  g_V[32 * 128];        // [k][row]  row: 0..63 re(z^(31-k)), 64..127 im
__device__ float  g_Mt[160 * 32];       // [K][t]    K<32: Toeplitz W (D folded); K>=32: carry proj
__device__ float  g_Pp[128 * NSEGS];    // planar P: rows 0..63 re, 64..127 im
__device__ float  g_Xc[128 * NSEGS];    // planar carries, same row layout
__device__ float2 g_a32[NMODES];        // z^32
__device__ float2 g_mk2[NMODES * LEVELS]; // z^(2048 * 2^k)
__device__ unsigned long long g_bar = 0;  // monotonic grid barrier (never reset)

// ---------------- fast z^e: double phase reduction + MUFU sin/cos ----------------
static __device__ __forceinline__ float2 cexp_pow(double dr, double di, double e) {
    float m = expf((float)(e * dr));
    double t = e * di;
    double q = rint(t * 0.15915494309189533576888376337251);
    double r = fma(q, -6.283185307179586476925286766559, t);
    float s, c;
    sincosf((float)r, &s, &c);
    return make_float2(m * c, m * s);
}

// ---------------- K0: constants + coefficient matrices ----------------
__global__ void k0_setup(const float* __restrict__ A_re,
                         const float* __restrict__ A_im,
                         const float* __restrict__ C,
                         const float* __restrict__ D,
                         const float* __restrict__ log_step) {
    __shared__ float sW[32 * 64];
    __shared__ float sWl[32];
    int t = threadIdx.x;             // 128 threads
    int m = t & 63;
    double dt = exp((double)log_step[0]);
    double ar = (double)A_re[m], ai = (double)A_im[m];
    double dr = dt * ar, di = dt * ai;

    float2 z1 = cexp_pow(dr, di, 1.0);
    double ctr = (double)C[2 * m], cti = (double)C[2 * m + 1];
    double wr = (double)z1.x - 1.0, wi = (double)z1.y;
    double den = ar * ar + ai * ai;
    double qr = (wr * ar + wi * ai) / den;
    double qi = (wi * ar - wr * ai) / den;
    float cfr = (float)(ctr * qr - cti * qi);
    float cfi = (float)(ctr * qi + cti * qr);

    if (t < 64) {
        g_a32[m] = cexp_pow(dr, di, 32.0);
        double e = 2048.0;
        for (int k = 0; k < LEVELS; k++) { g_mk2[m * LEVELS + k] = cexp_pow(dr, di, e); e *= 2.0; }
        for (int eI = 0; eI < 32; eI++) {
            float2 w = cexp_pow(dr, di, (double)eI);
            g_V[(31 - eI) * 128 + m]      = w.x;    // Re z^(31-k) at row m
            g_V[(31 - eI) * 128 + 64 + m] = w.y;
            sW[eI * 64 + m] = cfr * w.x - cfi * w.y;  // Re(c z^e)
        }
    } else {
        // carry projection rows: Mt[32+m][t] = Re(c z^{t+1}), Mt[96+m][t] = -Im(c z^{t+1})
        for (int tr = 0; tr < 32; tr++) {
            float2 w = cexp_pow(dr, di, (double)(tr + 1));
            g_Mt[(32 + m) * 32 + tr] = cfr * w.x - cfi * w.y;
            g_Mt[(96 + m) * 32 + tr] = -(cfr * w.y + cfi * w.x);
        }
    }
    __syncthreads();
    if (t < 32) {
        float s = 0.f;
        for (int mm = 0; mm < 64; mm++) s += sW[t * 64 + mm];
        sWl[t] = s;                  // W[l] = Re sum_n c_n z_n^l
    }
    __syncthreads();
    float Dv = D[0];
    for (int idx = t; idx < 1024; idx += 128) {
        int k = idx >> 5, tt = idx & 31;
        float v = (tt >= k) ? sWl[tt - k] : 0.f;
        if (tt == k) v += Dv;        // fold D*u into the Toeplitz diagonal
        g_Mt[k * 32 + tt] = v;
    }
}

// ---------------- grid barrier: monotonic counter (graph-replay safe) ----------------
static __device__ __forceinline__ void gridbar() {
    __syncthreads();
    if (threadIdx.x == 0) {
        __threadfence();
        unsigned long long tok = atomicAdd(&g_bar, 1ULL);
        unsigned long long target = (tok / GRID + 1ULL) * GRID;
        volatile unsigned long long* p = &g_bar;
        while (*p < target) __nanosleep(64);
        __threadfence();
    }
    __syncthreads();
}

// ---------------- scan step: E = a*E + P ----------------
#define BSTEP(Er, Ei, pr, pi)                          \
    do {                                               \
        float _tr = fmaf(-a.y, (Ei), (pr));            \
        float _ti = fmaf( a.y, (Er), (pi));            \
        (Er) = fmaf(a.x, (Er), _tr);                   \
        (Ei) = fmaf(a.x, (Ei), _ti);                   \
    } while (0)

// ---------------- fused main: P-GEMM -> scan -> Y-GEMM ----------------
__global__ void __launch_bounds__(THR, 4) kmain(const float* __restrict__ u,
                                                float* __restrict__ y) {
    __shared__ float sm[5376];       // 21.5 KB: phase-dependent layout
    int t = threadIdx.x, b = blockIdx.x;

    // ===== Phase A: P[128][8192] = V[128][32] @ U[32][8192], 8 segs/chunk =====
    {
        const float4* vsrc = (const float4*)g_V;
        float4* vdst = (float4*)sm;
        for (int i = t; i < 1024; i += THR) vdst[i] = vsrc[i];   // V -> sm[0..4095]
        int rq = t & 31, sp = t >> 5;
        for (int c = b; c < 1024; c += GRID) {
            __syncthreads();
            const float* ub = u + c * 256;
            for (int i = t; i < 256; i += THR)
                sm[4096 + (i & 31) * 8 + (i >> 5)] = ub[i];      // U[k][seg]
            __syncthreads();
            float a00 = 0.f, a10 = 0.f, a20 = 0.f, a30 = 0.f;
            float a01 = 0.f, a11 = 0.f, a21 = 0.f, a31 = 0.f;
#pragma unroll
            for (int k = 0; k < 32; k++) {
                float4 v  = *(const float4*)&sm[k * 128 + 4 * rq];
                float2 uu = *(const float2*)&sm[4096 + k * 8 + 2 * sp];
                a00 = fmaf(v.x, uu.x, a00); a01 = fmaf(v.x, uu.y, a01);
                a10 = fmaf(v.y, uu.x, a10); a11 = fmaf(v.y, uu.y, a11);
                a20 = fmaf(v.z, uu.x, a20); a21 = fmaf(v.z, uu.y, a21);
                a30 = fmaf(v.w, uu.x, a30); a31 = fmaf(v.w, uu.y, a31);
            }
            float* ps = &sm[4352 + (4 * rq) * 8 + 2 * sp];
            ps[0]  = a00; ps[1]  = a01;
            ps[8]  = a10; ps[9]  = a11;
            ps[16] = a20; ps[17] = a21;
            ps[24] = a30; ps[25] = a31;
            __syncthreads();
            float4* prow = (float4*)&g_Pp[t * NSEGS + c * 8];    // row t, 32B sector
            prow[0] = *(const float4*)&sm[4352 + t * 8];
            prow[1] = *(const float4*)&sm[4352 + t * 8 + 4];
            __syncthreads();
        }
    }
    gridbar();

    // ===== Phase B: per-mode scan over 8192 segs (blocks 0..63) =====
    if (b < 64) {
        int n = b;
        float2 a = g_a32[n];
        const float* pre = &g_Pp[n * NSEGS];
        const float* pim = &g_Pp[(64 + n) * NSEGS];
        int s0 = t * CPT;
        float Br = 0.f, Bi = 0.f;
        for (int j = 0; j < CPT; j += 4) {
            float4 r4 = *(const float4*)&pre[s0 + j];
            float4 i4 = *(const float4*)&pim[s0 + j];
            BSTEP(Br, Bi, r4.x, i4.x);
            BSTEP(Br, Bi, r4.y, i4.y);
            BSTEP(Br, Bi, r4.z, i4.z);
            BSTEP(Br, Bi, r4.w, i4.w);
        }
        sm[t] = Br; sm[128 + t] = Bi;
#pragma unroll
        for (int k = 0; k < LEVELS; k++) {
            int off = 1 << k;
            float2 mm = g_mk2[n * LEVELS + k];
            __syncthreads();
            float lr = 0.f, li = 0.f;
            if (t >= off) { lr = sm[t - off]; li = sm[128 + t - off]; }
            __syncthreads();
            if (t >= off) {
                float nr = fmaf(mm.x, lr, fmaf(-mm.y, li, Br));
                float ni = fmaf(mm.x, li, fmaf( mm.y, lr, Bi));
                Br = nr; Bi = ni;
                sm[t] = Br; sm[128 + t] = Bi;
            }
        }
        __syncthreads();
        float Er = 0.f, Ei = 0.f;
        if (t > 0) { Er = sm[t - 1]; Ei = sm[128 + t - 1]; }
        float* xre = &g_Xc[n * NSEGS];
        float* xim = &g_Xc[(64 + n) * NSEGS];
        for (int j = 0; j < CPT; j += 4) {
            float4 r4 = *(const float4*)&pre[s0 + j];
            float4 i4 = *(const float4*)&pim[s0 + j];
            float4 orv, oiv;
            orv.x = Er; oiv.x = Ei; BSTEP(Er, Ei, r4.x, i4.x);
            orv.y = Er; oiv.y = Ei; BSTEP(Er, Ei, r4.y, i4.y);
            orv.z = Er; oiv.z = Ei; BSTEP(Er, Ei, r4.z, i4.z);
            orv.w = Er; oiv.w = Ei; BSTEP(Er, Ei, r4.w, i4.w);
            *(float4*)&xre[s0 + j] = orv;
            *(float4*)&xim[s0 + j] = oiv;
        }
    }
    gridbar();

    // ===== Phase C: Y[32][32segs] = Mt[160][32]^T-dot-[U;Xc], blocks 0..255 =====
    if (b < 256) {
        int ss2 = b * 32;
        int tq = t & 7, sp2 = t >> 3;
        float a00 = 0.f, a10 = 0.f, a20 = 0.f, a30 = 0.f;
        float a01 = 0.f, a11 = 0.f, a21 = 0.f, a31 = 0.f;
        for (int p = 0; p < 2; p++) {
            __syncthreads();
            {   // stage Mt rows 80p..80p+79 -> sm[0..2559]
                const float4* src = (const float4*)&g_Mt[80 * p * 32];
                float4* dst = (float4*)&sm[0];
                for (int i = t; i < 640; i += THR) dst[i] = src[i];
            }
            if (p == 0) {   // R rows 0..31 = U^T, rows 32..79 = Xc rows 0..47
                const float* ub = u + ss2 * 32;
                for (int i = t; i < 1024; i += THR)
                    sm[2560 + (i & 31) * 32 + (i >> 5)] = ub[i];
                for (int lin = t; lin < 1536; lin += THR) {
                    int r = lin >> 5, s = lin & 31;
                    sm[2560 + (32 + r) * 32 + s] = g_Xc[r * NSEGS + ss2 + s];
                }
            } else {        // R rows 0..79 = Xc rows 48..127
                for (int lin = t; lin < 2560; lin += THR) {
                    int r = lin >> 5, s = lin & 31;
                    sm[2560 + r * 32 + s] = g_Xc[(48 + r) * NSEGS + ss2 + s];
                }
            }
            __syncthreads();
#pragma unroll 8
            for (int k = 0; k < 80; k++) {
                float4 mv = *(const float4*)&sm[k * 32 + 4 * tq];
                float2 rv = *(const float2*)&sm[2560 + k * 32 + 2 * sp2];
                a00 = fmaf(mv.x, rv.x, a00); a01 = fmaf(mv.x, rv.y, a01);
                a10 = fmaf(mv.y, rv.x, a10); a11 = fmaf(mv.y, rv.y, a11);
                a20 = fmaf(mv.z, rv.x, a20); a21 = fmaf(mv.z, rv.y, a21);
                a30 = fmaf(mv.w, rv.x, a30); a31 = fmaf(mv.w, rv.y, a31);
            }
        }
        int seg0 = ss2 + 2 * sp2;
        *(float4*)&y[seg0 * 32 + 4 * tq]       = make_float4(a00, a10, a20, a30);
        *(float4*)&y[(seg0 + 1) * 32 + 4 * tq] = make_float4(a01, a11, a21, a31);
    }
}

// ---------------- host ----------------
extern "C" void kernel_launch(void* const* d_in, const int* in_sizes, int n_in,
                              void* d_out, int out_size) {
    const float* u = 0; const float* A_re = 0; const float* A_im = 0;
    const float* C = 0; const float* D = 0; const float* log_step = 0;
    for (int i = 0; i < n_in; i++) {
        int sz = in_sizes[i];
        const float* p = (const float*)d_in[i];
        if (sz == LSEQ)            { if (!u) u = p; }
        else if (sz == 2 * NMODES) { if (!C) C = p; }
        else if (sz == NMODES)     { if (!A_re) A_re = p; else A_im = p; }
        else if (sz == 1)          { if (!D) D = p; else log_step = p; }
    }
    float* y = (float*)d_out;

    k0_setup<<<1, 128>>>(A_re, A_im, C, D, log_step);
    kmain<<<GRID, THR>>>(u, y);
}

// round 10
// speedup vs baseline: 1.0895x; 1.0895x over previous
#include <cuda_runtime.h>
#include <math.h>

#define NMODES 64
#define LSEQ   262144
#define SEG    32
#define NSEGS  (LSEQ/SEG)        /* 8192 */
#define LEVELS 9
#define SCAN_T 512
#define CPT    16                /* segs per scan thread */

// ---------------- scratch (static device globals; no allocation) ----------------
__device__ float  g_V[32 * 128];          // [k][row]  row: 0..63 re(z^(31-k)), 64..127 im
__device__ float  g_Mt[160 * 32];         // [K][t]    K<32: Toeplitz W (D folded); K>=32: carry proj
__device__ float  g_Pp[128 * NSEGS];      // planar P: rows 0..63 re, 64..127 im
__device__ float  g_Xc[128 * NSEGS];      // planar carries, same layout
__device__ float2 g_a32[NMODES];          // z^32
__device__ float2 g_mk2[NMODES * LEVELS]; // z^(512 * 2^k), k=0..8

// ---------------- fast z^e: double phase reduction + MUFU sin/cos ----------------
static __device__ __forceinline__ float2 cexp_pow(double dr, double di, double e) {
    float m = expf((float)(e * dr));
    double t = e * di;
    double q = rint(t * 0.15915494309189533576888376337251);
    double r = fma(q, -6.283185307179586476925286766559, t);
    float s, c;
    sincosf((float)r, &s, &c);
    return make_float2(m * c, m * s);
}

// ---------------- K0: constants + coefficient matrices (verified in R9) ----------------
__global__ void k0_setup(const float* __restrict__ A_re,
                         const float* __restrict__ A_im,
                         const float* __restrict__ C,
                         const float* __restrict__ D,
                         const float* __restrict__ log_step) {
    __shared__ float sW[32 * 64];
    __shared__ float sWl[32];
    int t = threadIdx.x;             // 128 threads
    int m = t & 63;
    double dt = exp((double)log_step[0]);
    double ar = (double)A_re[m], ai = (double)A_im[m];
    double dr = dt * ar, di = dt * ai;

    float2 z1 = cexp_pow(dr, di, 1.0);
    double ctr = (double)C[2 * m], cti = (double)C[2 * m + 1];
    double wr = (double)z1.x - 1.0, wi = (double)z1.y;
    double den = ar * ar + ai * ai;
    double qr = (wr * ar + wi * ai) / den;
    double qi = (wi * ar - wr * ai) / den;
    float cfr = (float)(ctr * qr - cti * qi);
    float cfi = (float)(ctr * qi + cti * qr);

    if (t < 64) {
        g_a32[m] = cexp_pow(dr, di, 32.0);
        double e = 512.0;
        for (int k = 0; k < LEVELS; k++) { g_mk2[m * LEVELS + k] = cexp_pow(dr, di, e); e *= 2.0; }
        for (int eI = 0; eI < 32; eI++) {
            float2 w = cexp_pow(dr, di, (double)eI);
            g_V[(31 - eI) * 128 + m]      = w.x;
            g_V[(31 - eI) * 128 + 64 + m] = w.y;
            sW[eI * 64 + m] = cfr * w.x - cfi * w.y;   // Re(c z^e)
        }
    } else {
        // carry projection rows: Mt[32+m][t] = Re(c z^{t+1}), Mt[96+m][t] = -Im(c z^{t+1})
        for (int tr = 0; tr < 32; tr++) {
            float2 w = cexp_pow(dr, di, (double)(tr + 1));
            g_Mt[(32 + m) * 32 + tr] = cfr * w.x - cfi * w.y;
            g_Mt[(96 + m) * 32 + tr] = -(cfr * w.y + cfi * w.x);
        }
    }
    __syncthreads();
    if (t < 32) {
        float s = 0.f;
        for (int mm = 0; mm < 64; mm++) s += sW[t * 64 + mm];
        sWl[t] = s;                  // W[l] = Re sum_n c_n z_n^l
    }
    __syncthreads();
    float Dv = D[0];
    for (int idx = t; idx < 1024; idx += 128) {
        int k = idx >> 5, tt = idx & 31;
        float v = (tt >= k) ? sWl[tt - k] : 0.f;
        if (tt == k) v += Dv;        // fold D*u into the Toeplitz diagonal
        g_Mt[k * 32 + tt] = v;
    }
}

// ---------------- kA: P[128][8192] = V[128][32] @ U[32][8192] ----------------
// grid = 1024 blocks x 128 thr; block handles 8 segs (256 samples).
__global__ void __launch_bounds__(128) kA_pgemm(const float* __restrict__ u) {
    __shared__ float sm[5376];
    int t = threadIdx.x, c = blockIdx.x;
    {
        const float4* vsrc = (const float4*)g_V;
        float4* vdst = (float4*)sm;
        for (int i = t; i < 1024; i += 128) vdst[i] = vsrc[i];   // V -> sm[0..4095]
    }
    const float* ub = u + c * 256;
    for (int i = t; i < 256; i += 128)
        sm[4096 + (i & 31) * 8 + (i >> 5)] = ub[i];              // U[k][seg]
    __syncthreads();

    int rq = t & 31, sp = t >> 5;
    float a00 = 0.f, a10 = 0.f, a20 = 0.f, a30 = 0.f;
    float a01 = 0.f, a11 = 0.f, a21 = 0.f, a31 = 0.f;
#pragma unroll
    for (int k = 0; k < 32; k++) {
        float4 v  = *(const float4*)&sm[k * 128 + 4 * rq];
        float2 uu = *(const float2*)&sm[4096 + k * 8 + 2 * sp];
        a00 = fmaf(v.x, uu.x, a00); a01 = fmaf(v.x, uu.y, a01);
        a10 = fmaf(v.y, uu.x, a10); a11 = fmaf(v.y, uu.y, a11);
        a20 = fmaf(v.z, uu.x, a20); a21 = fmaf(v.z, uu.y, a21);
        a30 = fmaf(v.w, uu.x, a30); a31 = fmaf(v.w, uu.y, a31);
    }
    float* ps = &sm[4352 + (4 * rq) * 8 + 2 * sp];
    ps[0]  = a00; ps[1]  = a01;
    ps[8]  = a10; ps[9]  = a11;
    ps[16] = a20; ps[17] = a21;
    ps[24] = a30; ps[25] = a31;
    __syncthreads();
    float4* prow = (float4*)&g_Pp[t * NSEGS + c * 8];            // row t, 32B
    prow[0] = *(const float4*)&sm[4352 + t * 8];
    prow[1] = *(const float4*)&sm[4352 + t * 8 + 4];
}

// ---------------- kB: per-mode fp32 scan over 8192 segs, emit carries ----------------
#define BSTEP(Er, Ei, pr, pi)                          \
    do {                                               \
        float _tr = fmaf(-a.y, (Ei), (pr));            \
        float _ti = fmaf( a.y, (Er), (pi));            \
        (Er) = fmaf(a.x, (Er), _tr);                   \
        (Ei) = fmaf(a.x, (Ei), _ti);                   \
    } while (0)

__global__ void __launch_bounds__(SCAN_T) kB_scan() {
    __shared__ float smr[SCAN_T];
    __shared__ float smi[SCAN_T];
    int n = blockIdx.x, t = threadIdx.x;
    float2 a = g_a32[n];
    const float* pre = &g_Pp[n * NSEGS];
    const float* pim = &g_Pp[(64 + n) * NSEGS];
    int s0 = t * CPT;

    float Br = 0.f, Bi = 0.f;
#pragma unroll
    for (int j = 0; j < CPT; j += 4) {
        float4 r4 = *(const float4*)&pre[s0 + j];
        float4 i4 = *(const float4*)&pim[s0 + j];
        BSTEP(Br, Bi, r4.x, i4.x);
        BSTEP(Br, Bi, r4.y, i4.y);
        BSTEP(Br, Bi, r4.z, i4.z);
        BSTEP(Br, Bi, r4.w, i4.w);
    }
    smr[t] = Br; smi[t] = Bi;
#pragma unroll
    for (int k = 0; k < LEVELS; k++) {
        int off = 1 << k;
        float2 mm = g_mk2[n * LEVELS + k];
        __syncthreads();
        float lr = 0.f, li = 0.f;
        if (t >= off) { lr = smr[t - off]; li = smi[t - off]; }
        __syncthreads();
        if (t >= off) {
            float nr = fmaf(mm.x, lr, fmaf(-mm.y, li, Br));
            float ni = fmaf(mm.x, li, fmaf( mm.y, lr, Bi));
            Br = nr; Bi = ni;
            smr[t] = Br; smi[t] = Bi;
        }
    }
    __syncthreads();
    float Er = 0.f, Ei = 0.f;
    if (t > 0) { Er = smr[t - 1]; Ei = smi[t - 1]; }
    float* xre = &g_Xc[n * NSEGS];
    float* xim = &g_Xc[(64 + n) * NSEGS];
#pragma unroll
    for (int j = 0; j < CPT; j += 4) {
        float4 r4 = *(const float4*)&pre[s0 + j];
        float4 i4 = *(const float4*)&pim[s0 + j];
        float4 orv, oiv;
        orv.x = Er; oiv.x = Ei; BSTEP(Er, Ei, r4.x, i4.x);
        orv.y = Er; oiv.y = Ei; BSTEP(Er, Ei, r4.y, i4.y);
        orv.z = Er; oiv.z = Ei; BSTEP(Er, Ei, r4.z, i4.z);
        orv.w = Er; oiv.w = Ei; BSTEP(Er, Ei, r4.w, i4.w);
        *(float4*)&xre[s0 + j] = orv;
        *(float4*)&xim[s0 + j] = oiv;
    }
}

// ---------------- kC: Y[32][segs] = Mt[160][32]^T dot [U;Xc] ----------------
// grid = 256 blocks x 256 thr; block handles 32 segs (1024 samples).
__global__ void __launch_bounds__(256) kC_ygemm(const float* __restrict__ u,
                                               float* __restrict__ y) {
    __shared__ float sm[5120];       // 20 KB: Mt stage 2560 + R stage 2560
    int t = threadIdx.x, b = blockIdx.x;
    int ss2 = b * 32;
    int tq = t & 7, sp = t >> 3;     // rows 4tq..4tq+3, seg sp (0..31)

    float a0 = 0.f, a1 = 0.f, a2 = 0.f, a3 = 0.f;
#pragma unroll
    for (int p = 0; p < 2; p++) {
        __syncthreads();
        {   // stage Mt rows 80p..80p+79
            const float4* src = (const float4*)&g_Mt[80 * p * 32];
            float4* dst = (float4*)&sm[0];
            for (int i = t; i < 640; i += 256) dst[i] = src[i];
        }
        if (p == 0) {   // R rows 0..31 = U^T, rows 32..79 = Xc rows 0..47
            const float* ub = u + ss2 * 32;
            for (int i = t; i < 1024; i += 256)
                sm[2560 + (i & 31) * 32 + (i >> 5)] = ub[i];
            for (int lin = t; lin < 1536; lin += 256) {
                int r = lin >> 5, s = lin & 31;
                sm[2560 + (32 + r) * 32 + s] = g_Xc[r * NSEGS + ss2 + s];
            }
        } else {        // R rows 0..79 = Xc rows 48..127
            for (int lin = t; lin < 2560; lin += 256) {
                int r = lin >> 5, s = lin & 31;
                sm[2560 + r * 32 + s] = g_Xc[(48 + r) * NSEGS + ss2 + s];
            }
        }
        __syncthreads();
#pragma unroll 8
        for (int k = 0; k < 80; k++) {
            float4 mv = *(const float4*)&sm[k * 32 + 4 * tq];
            float  rv = sm[2560 + k * 32 + sp];
            a0 = fmaf(mv.x, rv, a0);
            a1 = fmaf(mv.y, rv, a1);
            a2 = fmaf(mv.z, rv, a2);
            a3 = fmaf(mv.w, rv, a3);
        }
    }
    *(float4*)&y[(ss2 + sp) * 32 + 4 * tq] = make_float4(a0, a1, a2, a3);
}

// ---------------- host ----------------
extern "C" void kernel_launch(void* const* d_in, const int* in_sizes, int n_in,
                              void* d_out, int out_size) {
    const float* u = 0; const float* A_re = 0; const float* A_im = 0;
    const float* C = 0; const float* D = 0; const float* log_step = 0;
    for (int i = 0; i < n_in; i++) {
        int sz = in_sizes[i];
        const float* p = (const float*)d_in[i];
        if (sz == LSEQ)            { if (!u) u = p; }
        else if (sz == 2 * NMODES) { if (!C) C = p; }
        else if (sz == NMODES)     { if (!A_re) A_re = p; else A_im = p; }
        else if (sz == 1)          { if (!D) D = p; else log_step = p; }
    }
    float* y = (float*)d_out;

    k0_setup<<<1, 128>>>(A_re, A_im, C, D, log_step);
    kA_pgemm<<<NSEGS / 8, 128>>>(u);
    kB_scan<<<NMODES, SCAN_T>>>();
    kC_ygemm<<<NSEGS / 32, 256>>>(u, y);
}

// round 11
// speedup vs baseline: 1.2040x; 1.1052x over previous
#include <cuda_runtime.h>
#include <math.h>

#define NMODES 64
#define LSEQ   262144
#define SEG    32
#define NSEGS  (LSEQ/SEG)        /* 8192 */
#define LEVELS 9
#define SCAN_T 512
#define CPT    16                /* segs per scan thread */

// ---------------- scratch (static device globals; no allocation) ----------------
__device__ float  g_V[32 * 128];          // [k][row]  row: 0..63 re(z^(31-k)), 64..127 im
__device__ float  g_Mt[160 * 32];         // [K][t]    K<32: Toeplitz W (D folded); K>=32: carry proj
__device__ float  g_Pp[128 * NSEGS];      // planar P: rows 0..63 re, 64..127 im
__device__ float  g_Xc[128 * NSEGS];      // planar carries, same layout
__device__ float2 g_a32[NMODES];          // z^32
__device__ float2 g_mk2[NMODES * LEVELS]; // z^(512 * 2^k), k=0..8

// ---------------- fast z^e: double phase reduction + MUFU sin/cos ----------------
static __device__ __forceinline__ float2 cexp_pow(double dr, double di, double e) {
    float m = expf((float)(e * dr));
    double t = e * di;
    double q = rint(t * 0.15915494309189533576888376337251);
    double r = fma(q, -6.283185307179586476925286766559, t);
    float s, c;
    sincosf((float)r, &s, &c);
    return make_float2(m * c, m * s);
}

// ---------------- K0: constants + coefficient matrices (verified) ----------------
__global__ void k0_setup(const float* __restrict__ A_re,
                         const float* __restrict__ A_im,
                         const float* __restrict__ C,
                         const float* __restrict__ D,
                         const float* __restrict__ log_step) {
    __shared__ float sW[32 * 64];
    __shared__ float sWl[32];
    int t = threadIdx.x;             // 128 threads
    int m = t & 63;
    double dt = exp((double)log_step[0]);
    double ar = (double)A_re[m], ai = (double)A_im[m];
    double dr = dt * ar, di = dt * ai;

    float2 z1 = cexp_pow(dr, di, 1.0);
    double ctr = (double)C[2 * m], cti = (double)C[2 * m + 1];
    double wr = (double)z1.x - 1.0, wi = (double)z1.y;
    double den = ar * ar + ai * ai;
    double qr = (wr * ar + wi * ai) / den;
    double qi = (wi * ar - wr * ai) / den;
    float cfr = (float)(ctr * qr - cti * qi);
    float cfi = (float)(ctr * qi + cti * qr);

    if (t < 64) {
        g_a32[m] = cexp_pow(dr, di, 32.0);
        double e = 512.0;
        for (int k = 0; k < LEVELS; k++) { g_mk2[m * LEVELS + k] = cexp_pow(dr, di, e); e *= 2.0; }
        for (int eI = 0; eI < 32; eI++) {
            float2 w = cexp_pow(dr, di, (double)eI);
            g_V[(31 - eI) * 128 + m]      = w.x;
            g_V[(31 - eI) * 128 + 64 + m] = w.y;
            sW[eI * 64 + m] = cfr * w.x - cfi * w.y;   // Re(c z^e)
        }
    } else {
        // carry projection rows: Mt[32+m][t] = Re(c z^{t+1}), Mt[96+m][t] = -Im(c z^{t+1})
        for (int tr = 0; tr < 32; tr++) {
            float2 w = cexp_pow(dr, di, (double)(tr + 1));
            g_Mt[(32 + m) * 32 + tr] = cfr * w.x - cfi * w.y;
            g_Mt[(96 + m) * 32 + tr] = -(cfr * w.y + cfi * w.x);
        }
    }
    __syncthreads();
    if (t < 32) {
        float s = 0.f;
        for (int mm = 0; mm < 64; mm++) s += sW[t * 64 + mm];
        sWl[t] = s;                  // W[l] = Re sum_n c_n z_n^l
    }
    __syncthreads();
    float Dv = D[0];
    for (int idx = t; idx < 1024; idx += 128) {
        int k = idx >> 5, tt = idx & 31;
        float v = (tt >= k) ? sWl[tt - k] : 0.f;
        if (tt == k) v += Dv;        // fold D*u into the Toeplitz diagonal
        g_Mt[k * 32 + tt] = v;
    }
}

// ---------------- kA: P[128][8192] = V[128][32] @ U[32][8192], row/thread ----------------
// grid = 1024 blocks x 128 thr; block handles 8 segs (256 samples). Also zeroes y.
__global__ void __launch_bounds__(128) kA_pgemm(const float* __restrict__ u,
                                               float* __restrict__ y) {
    __shared__ float sV[4096];
    __shared__ float sU[32 * 12];    // stride 12: float4-aligned, conflict-light
    int t = threadIdx.x, c = blockIdx.x;
    {
        const float4* vs = (const float4*)g_V;
        float4* vd = (float4*)sV;
        for (int i = t; i < 1024; i += 128) vd[i] = vs[i];
    }
    const float* ub = u + c * 256;
    for (int i = t; i < 256; i += 128) {
        int seg = i >> 5, k = i & 31;
        sU[k * 12 + seg] = ub[i];
    }
    ((float2*)y)[c * 128 + t] = make_float2(0.f, 0.f);   // zero y for kC's RED.ADD
    __syncthreads();

    float a0 = 0.f, a1 = 0.f, a2 = 0.f, a3 = 0.f;
    float a4 = 0.f, a5 = 0.f, a6 = 0.f, a7 = 0.f;
#pragma unroll
    for (int k = 0; k < 32; k++) {
        float  v  = sV[k * 128 + t];                     // conflict-free
        float4 u0 = *(const float4*)&sU[k * 12];         // broadcast
        float4 u1 = *(const float4*)&sU[k * 12 + 4];     // broadcast
        a0 = fmaf(v, u0.x, a0); a1 = fmaf(v, u0.y, a1);
        a2 = fmaf(v, u0.z, a2); a3 = fmaf(v, u0.w, a3);
        a4 = fmaf(v, u1.x, a4); a5 = fmaf(v, u1.y, a5);
        a6 = fmaf(v, u1.z, a6); a7 = fmaf(v, u1.w, a7);
    }
    float4* pr = (float4*)&g_Pp[t * NSEGS + c * 8];      // direct, 32B/thread
    pr[0] = make_float4(a0, a1, a2, a3);
    pr[1] = make_float4(a4, a5, a6, a7);
}

// ---------------- kB: per-mode fp32 scan over 8192 segs, emit carries ----------------
#define BSTEP(Er, Ei, pr, pi)                          \
    do {                                               \
        float _tr = fmaf(-a.y, (Ei), (pr));            \
        float _ti = fmaf( a.y, (Er), (pi));            \
        (Er) = fmaf(a.x, (Er), _tr);                   \
        (Ei) = fmaf(a.x, (Ei), _ti);                   \
    } while (0)

__global__ void __launch_bounds__(SCAN_T) kB_scan() {
    __shared__ float smr[SCAN_T];
    __shared__ float smi[SCAN_T];
    int n = blockIdx.x, t = threadIdx.x;
    float2 a = g_a32[n];
    const float* pre = &g_Pp[n * NSEGS];
    const float* pim = &g_Pp[(64 + n) * NSEGS];
    int s0 = t * CPT;

    float Br = 0.f, Bi = 0.f;
#pragma unroll
    for (int j = 0; j < CPT; j += 4) {
        float4 r4 = *(const float4*)&pre[s0 + j];
        float4 i4 = *(const float4*)&pim[s0 + j];
        BSTEP(Br, Bi, r4.x, i4.x);
        BSTEP(Br, Bi, r4.y, i4.y);
        BSTEP(Br, Bi, r4.z, i4.z);
        BSTEP(Br, Bi, r4.w, i4.w);
    }
    smr[t] = Br; smi[t] = Bi;
#pragma unroll
    for (int k = 0; k < LEVELS; k++) {
        int off = 1 << k;
        float2 mm = g_mk2[n * LEVELS + k];
        __syncthreads();
        float lr = 0.f, li = 0.f;
        if (t >= off) { lr = smr[t - off]; li = smi[t - off]; }
        __syncthreads();
        if (t >= off) {
            float nr = fmaf(mm.x, lr, fmaf(-mm.y, li, Br));
            float ni = fmaf(mm.x, li, fmaf( mm.y, lr, Bi));
            Br = nr; Bi = ni;
            smr[t] = Br; smi[t] = Bi;
        }
    }
    __syncthreads();
    float Er = 0.f, Ei = 0.f;
    if (t > 0) { Er = smr[t - 1]; Ei = smi[t - 1]; }
    float* xre = &g_Xc[n * NSEGS];
    float* xim = &g_Xc[(64 + n) * NSEGS];
#pragma unroll
    for (int j = 0; j < CPT; j += 4) {
        float4 r4 = *(const float4*)&pre[s0 + j];
        float4 i4 = *(const float4*)&pim[s0 + j];
        float4 orv, oiv;
        orv.x = Er; oiv.x = Ei; BSTEP(Er, Ei, r4.x, i4.x);
        orv.y = Er; oiv.y = Ei; BSTEP(Er, Ei, r4.y, i4.y);
        orv.z = Er; oiv.z = Ei; BSTEP(Er, Ei, r4.z, i4.z);
        orv.w = Er; oiv.w = Ei; BSTEP(Er, Ei, r4.w, i4.w);
        *(float4*)&xre[s0 + j] = orv;
        *(float4*)&xim[s0 + j] = oiv;
    }
}

// ---------------- kC: Y[32][8192] = Mt[160][32]^T @ [U;Xc], K-split x2, reg-tiled ----------------
// grid = 256 (128 seg-chunks x 2 K-halves) x 128 thr; thread = 4 rows x 4 segs.
__global__ void __launch_bounds__(128) kC_ygemm(const float* __restrict__ u,
                                               float* __restrict__ y) {
    __shared__ float sMt[80 * 32];   // 10 KB
    __shared__ float sR[80 * 68];    // 21.8 KB, stride 68 (float4-aligned)
    int t = threadIdx.x;
    int chunk = blockIdx.x >> 1, kh = blockIdx.x & 1;
    int ss = chunk * 64;

    {   // stage Mt rows kh*80 .. +80
        const float4* src = (const float4*)&g_Mt[kh * 80 * 32];
        float4* dst = (float4*)sMt;
        for (int i = t; i < 640; i += 128) dst[i] = src[i];
    }
    if (kh == 0) {   // R rows 0..31 = U^T, rows 32..79 = Xc rows 0..47
        const float* ub = u + ss * 32;
        for (int i = t; i < 2048; i += 128) {
            int seg = i >> 5, k = i & 31;
            sR[k * 68 + seg] = ub[i];
        }
        for (int lin = t; lin < 48 * 64; lin += 128) {
            int r = lin >> 6, s = lin & 63;
            sR[(32 + r) * 68 + s] = g_Xc[r * NSEGS + ss + s];
        }
    } else {         // R rows 0..79 = Xc rows 48..127
        for (int lin = t; lin < 80 * 64; lin += 128) {
            int r = lin >> 6, s = lin & 63;
            sR[r * 68 + s] = g_Xc[(48 + r) * NSEGS + ss + s];
        }
    }
    __syncthreads();

    int tq = t & 7, sp = t >> 3;     // rows 4tq..+3, segs 4sp..+3
    float c00 = 0.f, c01 = 0.f, c02 = 0.f, c03 = 0.f;
    float c10 = 0.f, c11 = 0.f, c12 = 0.f, c13 = 0.f;
    float c20 = 0.f, c21 = 0.f, c22 = 0.f, c23 = 0.f;
    float c30 = 0.f, c31 = 0.f, c32 = 0.f, c33 = 0.f;
#pragma unroll 4
    for (int k = 0; k < 80; k++) {
        float4 mv = *(const float4*)&sMt[k * 32 + 4 * tq];
        float4 rv = *(const float4*)&sR[k * 68 + 4 * sp];
        c00 = fmaf(mv.x, rv.x, c00); c01 = fmaf(mv.x, rv.y, c01);
        c02 = fmaf(mv.x, rv.z, c02); c03 = fmaf(mv.x, rv.w, c03);
        c10 = fmaf(mv.y, rv.x, c10); c11 = fmaf(mv.y, rv.y, c11);
        c12 = fmaf(mv.y, rv.z, c12); c13 = fmaf(mv.y, rv.w, c13);
        c20 = fmaf(mv.z, rv.x, c20); c21 = fmaf(mv.z, rv.y, c21);
        c22 = fmaf(mv.z, rv.z, c22); c23 = fmaf(mv.z, rv.w, c23);
        c30 = fmaf(mv.w, rv.x, c30); c31 = fmaf(mv.w, rv.y, c31);
        c32 = fmaf(mv.w, rv.z, c32); c33 = fmaf(mv.w, rv.w, c33);
    }
    // combine the two K-halves: exactly 2 commutative adds onto 0 -> deterministic
    float* y0 = &y[(ss + 4 * sp + 0) * 32 + 4 * tq];
    float* y1 = &y[(ss + 4 * sp + 1) * 32 + 4 * tq];
    float* y2 = &y[(ss + 4 * sp + 2) * 32 + 4 * tq];
    float* y3 = &y[(ss + 4 * sp + 3) * 32 + 4 * tq];
    atomicAdd(y0 + 0, c00); atomicAdd(y0 + 1, c10); atomicAdd(y0 + 2, c20); atomicAdd(y0 + 3, c30);
    atomicAdd(y1 + 0, c01); atomicAdd(y1 + 1, c11); atomicAdd(y1 + 2, c21); atomicAdd(y1 + 3, c31);
    atomicAdd(y2 + 0, c02); atomicAdd(y2 + 1, c12); atomicAdd(y2 + 2, c22); atomicAdd(y2 + 3, c32);
    atomicAdd(y3 + 0, c03); atomicAdd(y3 + 1, c13); atomicAdd(y3 + 2, c23); atomicAdd(y3 + 3, c33);
}

// ---------------- host ----------------
extern "C" void kernel_launch(void* const* d_in, const int* in_sizes, int n_in,
                              void* d_out, int out_size) {
    const float* u = 0; const float* A_re = 0; const float* A_im = 0;
    const float* C = 0; const float* D = 0; const float* log_step = 0;
    for (int i = 0; i < n_in; i++) {
        int sz = in_sizes[i];
        const float* p = (const float*)d_in[i];
        if (sz == LSEQ)            { if (!u) u = p; }
        else if (sz == 2 * NMODES) { if (!C) C = p; }
        else if (sz == NMODES)     { if (!A_re) A_re = p; else A_im = p; }
        else if (sz == 1)          { if (!D) D = p; else log_step = p; }
    }
    float* y = (float*)d_out;

    k0_setup<<<1, 128>>>(A_re, A_im, C, D, log_step);
    kA_pgemm<<<NSEGS / 8, 128>>>(u, y);
    kB_scan<<<NMODES, SCAN_T>>>();
    kC_ygemm<<<256, 128>>>(u, y);
}